// round 1
// baseline (speedup 1.0000x reference)
#include <cuda_runtime.h>
#include <cstdint>

#define B_ROWS 16384
#define NDIM   4096
#define KDIM   784
#define TOPK   64

// ---- scratch (no allocations allowed) ----
__device__ float g_Wt[NDIM * KDIM];        // W transposed: Wt[m][d] = W[d][m]
__device__ int   g_cnt[B_ROWS];
__device__ int   g_idx[B_ROWS * TOPK];
__device__ float g_val[B_ROWS * TOPK];
__device__ int   g_total;

// ---------------- packed f32x2 helpers (sm_103a FFMA2) ----------------
__device__ __forceinline__ void ffma2(unsigned long long& d,
                                      unsigned long long a,
                                      unsigned long long b) {
    asm("fma.rn.f32x2 %0, %1, %2, %3;" : "=l"(d) : "l"(a), "l"(b), "l"(d));
}
__device__ __forceinline__ unsigned long long dup2(float a) {
    unsigned long long r;
    asm("mov.b64 %0, {%1, %1};" : "=l"(r) : "f"(a));
    return r;
}
__device__ __forceinline__ void unpack2(unsigned long long v, float& lo, float& hi) {
    asm("mov.b64 {%0, %1}, %2;" : "=f"(lo), "=f"(hi) : "l"(v));
}

// ---------------- K0: transpose W + zero counter ----------------
__global__ void transpose_kernel(const float* __restrict__ W) {
    __shared__ float tile[32][33];
    int m0 = blockIdx.x * 32;   // M (output row) dim
    int d0 = blockIdx.y * 32;   // D dim
    int tx = threadIdx.x, ty = threadIdx.y;   // 32 x 8
#pragma unroll
    for (int i = 0; i < 32; i += 8) {
        int d = d0 + ty + i;
        if (d < KDIM) tile[ty + i][tx] = W[(size_t)d * NDIM + m0 + tx];
    }
    __syncthreads();
#pragma unroll
    for (int i = 0; i < 32; i += 8) {
        int d = d0 + tx;
        if (d < KDIM) g_Wt[(size_t)(m0 + ty + i) * KDIM + d] = tile[tx][ty + i];
    }
    if (blockIdx.x == 0 && blockIdx.y == 0 && tx == 0 && ty == 0) g_total = 0;
}

// ---------------- K1: encoder GEMM (fp32, FFMA2) ----------------
// C[16384,4096] = x[16384,784] @ W[784,4096] + b1
#define BM 128
#define BN 128
#define BK 16

__global__ __launch_bounds__(256, 2)
void encoder_gemm(const float* __restrict__ x, const float* __restrict__ W,
                  const float* __restrict__ b1, float* __restrict__ enc) {
    __shared__ float Xs[BK][BM];
    __shared__ float Ws[BK][BN];
    const int tid = threadIdx.x;
    const int tx = tid & 15;     // 0..15 -> 8 cols each
    const int ty = tid >> 4;     // 0..15 -> 8 rows each
    const int m0 = blockIdx.y * BM;
    const int n0 = blockIdx.x * BN;

    unsigned long long acc[8][4];
#pragma unroll
    for (int i = 0; i < 8; i++)
#pragma unroll
        for (int j = 0; j < 4; j++) acc[i][j] = 0ull;

    for (int kt = 0; kt < KDIM; kt += BK) {
        // load tiles (512 float4 each, 2 per thread)
#pragma unroll
        for (int l = 0; l < 2; l++) {
            int f = tid + 256 * l;
            int r  = f >> 2, kq = f & 3;
            float4 v = *(const float4*)(x + (size_t)(m0 + r) * KDIM + kt + kq * 4);
            Xs[kq * 4 + 0][r] = v.x;
            Xs[kq * 4 + 1][r] = v.y;
            Xs[kq * 4 + 2][r] = v.z;
            Xs[kq * 4 + 3][r] = v.w;
            int wr = f >> 5, nq = f & 31;
            *(float4*)&Ws[wr][nq * 4] =
                *(const float4*)(W + (size_t)(kt + wr) * NDIM + n0 + nq * 4);
        }
        __syncthreads();
#pragma unroll
        for (int k = 0; k < BK; k++) {
            float4 a0 = *(const float4*)&Xs[k][ty * 8];
            float4 a1 = *(const float4*)&Xs[k][ty * 8 + 4];
            unsigned long long bb[4];
#pragma unroll
            for (int j = 0; j < 4; j++)
                bb[j] = *(const unsigned long long*)&Ws[k][tx * 8 + 2 * j];
            float av[8] = {a0.x, a0.y, a0.z, a0.w, a1.x, a1.y, a1.z, a1.w};
#pragma unroll
            for (int i = 0; i < 8; i++) {
                unsigned long long aa = dup2(av[i]);
#pragma unroll
                for (int j = 0; j < 4; j++) ffma2(acc[i][j], aa, bb[j]);
            }
        }
        __syncthreads();
    }

    // epilogue: + b1, store
    float4 bias0 = *(const float4*)(b1 + n0 + tx * 8);
    float4 bias1 = *(const float4*)(b1 + n0 + tx * 8 + 4);
#pragma unroll
    for (int i = 0; i < 8; i++) {
        float c[8];
        unpack2(acc[i][0], c[0], c[1]);
        unpack2(acc[i][1], c[2], c[3]);
        unpack2(acc[i][2], c[4], c[5]);
        unpack2(acc[i][3], c[6], c[7]);
        float4 o0 = make_float4(c[0] + bias0.x, c[1] + bias0.y,
                                c[2] + bias0.z, c[3] + bias0.w);
        float4 o1 = make_float4(c[4] + bias1.x, c[5] + bias1.y,
                                c[6] + bias1.z, c[7] + bias1.w);
        float* er = enc + (size_t)(m0 + ty * 8 + i) * NDIM + n0 + tx * 8;
        *(float4*)er       = o0;
        *(float4*)(er + 4) = o1;
    }
}

// ---------------- K2: exact top-(K+1) threshold + res + compact ----------------
__global__ __launch_bounds__(256)
void topk_kernel(const float* __restrict__ enc, float* __restrict__ res) {
    const int row = blockIdx.x;
    const int tid = threadIdx.x;
    const float* er = enc + (size_t)row * NDIM;

    float v[16];
    unsigned int ab[16];
#pragma unroll
    for (int i = 0; i < 16; i++) {
        v[i]  = er[tid + 256 * i];
        ab[i] = __float_as_uint(v[i]) & 0x7fffffffu;
    }

    __shared__ int s_warp[8];
    __shared__ int s_total;
    __shared__ int s_slot;

    // binary search for T = 65th-largest abs-bits (bits order == float order for abs)
    unsigned int lo = 0u, hi = 0x7f800000u;   // cnt_ge(lo) >= 65 true, cnt_ge(hi)=0 false
    while (hi - lo > 1u) {
        unsigned int mid = lo + ((hi - lo) >> 1);
        int c = 0;
#pragma unroll
        for (int i = 0; i < 16; i++) c += (ab[i] >= mid);
#pragma unroll
        for (int o = 16; o; o >>= 1) c += __shfl_xor_sync(0xffffffffu, c, o);
        if ((tid & 31) == 0) s_warp[tid >> 5] = c;
        __syncthreads();
        if (tid == 0) {
            int t = 0;
#pragma unroll
            for (int w = 0; w < 8; w++) t += s_warp[w];
            s_total = t;
        }
        __syncthreads();
        if ((unsigned)s_total >= 65u) lo = mid; else hi = mid;
    }
    const unsigned int T = lo;

    if (tid == 0) s_slot = 0;
    __syncthreads();

    float* rr = res + (size_t)row * NDIM;
    const int base = row * TOPK;
#pragma unroll
    for (int i = 0; i < 16; i++) {
        bool act = (ab[i] > T);
        rr[tid + 256 * i] = act ? v[i] : 0.0f;
        if (act) {
            int s = atomicAdd(&s_slot, 1);
            g_idx[base + s] = tid + 256 * i;
            g_val[base + s] = v[i];
        }
    }
    __syncthreads();
    if (tid == 0) {
        g_cnt[row] = s_slot;
        atomicAdd(&g_total, s_slot);
    }
}

// ---------------- K3: sparse decoder + nnz ----------------
__global__ __launch_bounds__(256)
void decoder_kernel(const float* __restrict__ b2, float* __restrict__ dec,
                    float* __restrict__ nnz_out) {
    const int row = blockIdx.x;
    const int tid = threadIdx.x;
    __shared__ int   s_idx[TOPK];
    __shared__ float s_val[TOPK];
    const int c = g_cnt[row];
    if (tid < TOPK && tid < c) {
        s_idx[tid] = g_idx[row * TOPK + tid];
        s_val[tid] = g_val[row * TOPK + tid];
    }
    __syncthreads();

    const int d0 = tid, d1 = tid + 256, d2 = tid + 512, d3 = tid + 768;
    const bool has3 = (d3 < KDIM);
    float a0 = b2[d0], a1 = b2[d1], a2 = b2[d2];
    float a3 = has3 ? b2[d3] : 0.0f;

#pragma unroll 4
    for (int j = 0; j < c; j++) {
        const float* wr = g_Wt + (size_t)s_idx[j] * KDIM;
        const float val = s_val[j];
        a0 = fmaf(val, wr[d0], a0);
        a1 = fmaf(val, wr[d1], a1);
        a2 = fmaf(val, wr[d2], a2);
        if (has3) a3 = fmaf(val, wr[d3], a3);
    }
    float* dr = dec + (size_t)row * KDIM;
    dr[d0] = a0; dr[d1] = a1; dr[d2] = a2;
    if (has3) dr[d3] = a3;

    if (row == 0 && tid == 0)
        nnz_out[0] = (float)g_total / (float)B_ROWS;
}

// ---------------- launch ----------------
extern "C" void kernel_launch(void* const* d_in, const int* in_sizes, int n_in,
                              void* d_out, int out_size) {
    const float* x  = (const float*)d_in[0];
    const float* W  = (const float*)d_in[1];
    const float* b1 = (const float*)d_in[2];
    const float* b2 = (const float*)d_in[3];

    float* out = (float*)d_out;
    float* enc = out;                                        // 16384*4096
    float* dec = out + (size_t)B_ROWS * NDIM;                // 16384*784
    float* nnz = dec + (size_t)B_ROWS * KDIM;                // 1
    float* res = nnz + 1;                                    // 16384*4096

    transpose_kernel<<<dim3(NDIM / 32, (KDIM + 31) / 32), dim3(32, 8)>>>(W);
    encoder_gemm<<<dim3(NDIM / BN, B_ROWS / BM), 256>>>(x, W, b1, enc);
    topk_kernel<<<B_ROWS, 256>>>(enc, res);
    decoder_kernel<<<B_ROWS, 256>>>(b2, dec, nnz);
}